// round 3
// baseline (speedup 1.0000x reference)
#include <cuda_runtime.h>
#include <math.h>

// ---------------- problem constants ----------------
#define BB 2
#define SS 64
#define LL 256
#define CC 192
#define C4 768
#define HH 4
#define DH 48
#define TT (BB*SS*LL)      // 32768 tokens
#define NBLK 6

// ---------------- scratch ----------------
__device__ float g_x[TT*CC];
__device__ float g_h[TT*CC];
__device__ float g_q[TT*CC];
__device__ float g_k[TT*CC];
__device__ float g_v[TT*CC];
__device__ float g_f1[TT*C4];

__device__ __forceinline__ float elu1(float v) { return v > 0.0f ? v + 1.0f : expf(v); }
__device__ __forceinline__ float gelu_exact(float v) {
    return 0.5f * v * (1.0f + erff(v * 0.70710678118654752f));
}

// ============================================================
// Kernel 1: embed + proj + rotary
// ============================================================
__global__ void embed_kernel(const int* __restrict__ tokens,
                             const float* __restrict__ emb,
                             const float* __restrict__ pw,
                             const float* __restrict__ pb,
                             float* __restrict__ out) {
    int t = blockIdx.x;
    int c = threadIdx.x;
    __shared__ float e[64];
    __shared__ float xv[CC];
    __shared__ float invf[96];
    if (c < 64) e[c] = emb[tokens[t] * 64 + c];
    if (c >= 64 && c < 160) {
        int j = c - 64;
        invf[j] = powf(10000.0f, -(float)j / 96.0f);
    }
    __syncthreads();
    float s = pb[c];
    const float* wr = pw + c * 64;
    #pragma unroll
    for (int i = 0; i < 64; i++) s += e[i] * wr[i];
    xv[c] = s;
    __syncthreads();
    int l = t & (LL - 1);
    int c2 = (c < 96) ? c : c - 96;
    float a = (float)l * invf[c2];
    float cs = cosf(a), sn = sinf(a);
    float rot = (c < 96) ? -xv[c + 96] : xv[c - 96];
    out[(size_t)t * CC + c] = s * cs + rot * sn;
}

// ============================================================
// Kernel 2: LayerNorm over channels
// ============================================================
__global__ void ln_kernel(const float* __restrict__ x, float* __restrict__ h,
                          const float* __restrict__ g, const float* __restrict__ b) {
    int t = blockIdx.x * 8 + threadIdx.y;
    int lane = threadIdx.x;
    const float* xr = x + (size_t)t * CC;
    float v[6];
    float s = 0.f, ss = 0.f;
    #pragma unroll
    for (int i = 0; i < 6; i++) {
        v[i] = xr[lane + i * 32];
        s += v[i]; ss += v[i] * v[i];
    }
    #pragma unroll
    for (int o = 16; o; o >>= 1) {
        s  += __shfl_xor_sync(0xffffffffu, s, o);
        ss += __shfl_xor_sync(0xffffffffu, ss, o);
    }
    float m   = s * (1.0f / CC);
    float var = ss * (1.0f / CC) - m * m;
    float r   = rsqrtf(var + 1e-5f);
    float* hr = h + (size_t)t * CC;
    #pragma unroll
    for (int i = 0; i < 6; i++) {
        int c = lane + i * 32;
        hr[c] = (v[i] - m) * r * g[c] + b[c];
    }
}

// ============================================================
// TF32 tensor-core GEMM body, fragment-major shared layout.
// C[t,o] = act( A[t,:K] . W[o,:K] + bias[o] ) (+C)
// Block tile 128x64, 8 warps (4x2), warp 32x32, mma m16n8k8 tf32.
// Shared A: [mtile(8)][ktile(2)][lane(32)][slot(4)]  (float4 per lane)
// Shared B: [ntile(8)][ktile(2)][lane(32)][slot(2)]  (float2 per lane)
// ============================================================
#define BM 128
#define BN 64
#define BK 16

__device__ __forceinline__ void gemm_body(
        const float* __restrict__ A, const float* __restrict__ W,
        const float* __restrict__ bias, float* __restrict__ Cout,
        int K, int N, int act, int accFlag, int rowBlk, int colBlk,
        float* As, float* Bs) {
    int tid  = threadIdx.x;
    int lane = tid & 31;
    int warp = tid >> 5;
    int warpM = warp >> 1;
    int warpN = warp & 1;
    int gid = lane >> 2;
    int tig = lane & 3;
    int row0 = rowBlk * BM;
    int col0 = colBlk * BN;

    float acc[2][4][4];
    #pragma unroll
    for (int i = 0; i < 2; i++)
        #pragma unroll
        for (int j = 0; j < 4; j++)
            #pragma unroll
            for (int q = 0; q < 4; q++) acc[i][j][q] = 0.f;

    // staging indices
    int am = tid >> 1;                 // with i-loop: lin = tid + i*256 -> m = lin>>2... use explicit below
    (void)am;
    float4 aPre[2]; float4 bPre;
    {   // preload k0 = 0
        #pragma unroll
        for (int i = 0; i < 2; i++) {
            int lin = tid + i * 256;
            int m  = lin >> 2;
            int kq = (lin & 3) << 2;
            aPre[i] = *(const float4*)&A[(size_t)(row0 + m) * K + kq];
        }
        int n  = tid >> 2;
        int kq = (tid & 3) << 2;
        bPre = *(const float4*)&W[(size_t)(col0 + n) * K + kq];
    }

    for (int k0 = 0; k0 < K; k0 += BK) {
        // ---- store staged regs into fragment-major smem ----
        #pragma unroll
        for (int i = 0; i < 2; i++) {
            int lin = tid + i * 256;
            int m  = lin >> 2;
            int kq = (lin & 3) << 2;
            int mtile = m >> 4, r = m & 15;
            float fv[4] = {aPre[i].x, aPre[i].y, aPre[i].z, aPre[i].w};
            #pragma unroll
            for (int j = 0; j < 4; j++) {
                int k = kq + j;
                int ktile = k >> 3, kk = k & 7;
                int idx = (((mtile * 2 + ktile) * 32) + (r & 7) * 4 + (kk & 3)) * 4
                          + (r >> 3) + ((kk >> 2) << 1);
                As[idx] = fv[j];
            }
        }
        {
            int n  = tid >> 2;
            int kq = (tid & 3) << 2;
            int ntile = n >> 3, c = n & 7;
            float fv[4] = {bPre.x, bPre.y, bPre.z, bPre.w};
            #pragma unroll
            for (int j = 0; j < 4; j++) {
                int k = kq + j;
                int ktile = k >> 3, kk = k & 7;
                int idx = (((ntile * 2 + ktile) * 32) + c * 4 + (kk & 3)) * 2 + (kk >> 2);
                Bs[idx] = fv[j];
            }
        }
        __syncthreads();

        // ---- prefetch next k-tile ----
        if (k0 + BK < K) {
            #pragma unroll
            for (int i = 0; i < 2; i++) {
                int lin = tid + i * 256;
                int m  = lin >> 2;
                int kq = (lin & 3) << 2;
                aPre[i] = *(const float4*)&A[(size_t)(row0 + m) * K + k0 + BK + kq];
            }
            int n  = tid >> 2;
            int kq = (tid & 3) << 2;
            bPre = *(const float4*)&W[(size_t)(col0 + n) * K + k0 + BK + kq];
        }

        // ---- compute ----
        #pragma unroll
        for (int ktile = 0; ktile < 2; ktile++) {
            float4 af[2]; float2 bf[4];
            #pragma unroll
            for (int mt = 0; mt < 2; mt++) {
                int mtile = warpM * 2 + mt;
                af[mt] = ((const float4*)As)[(mtile * 2 + ktile) * 32 + lane];
            }
            #pragma unroll
            for (int nt = 0; nt < 4; nt++) {
                int ntile = warpN * 4 + nt;
                bf[nt] = ((const float2*)Bs)[(ntile * 2 + ktile) * 32 + lane];
            }
            #pragma unroll
            for (int mt = 0; mt < 2; mt++)
                #pragma unroll
                for (int nt = 0; nt < 4; nt++) {
                    asm volatile(
                        "mma.sync.aligned.m16n8k8.row.col.f32.tf32.tf32.f32 "
                        "{%0,%1,%2,%3}, {%4,%5,%6,%7}, {%8,%9}, {%0,%1,%2,%3};"
                        : "+f"(acc[mt][nt][0]), "+f"(acc[mt][nt][1]),
                          "+f"(acc[mt][nt][2]), "+f"(acc[mt][nt][3])
                        : "r"(__float_as_uint(af[mt].x)), "r"(__float_as_uint(af[mt].y)),
                          "r"(__float_as_uint(af[mt].z)), "r"(__float_as_uint(af[mt].w)),
                          "r"(__float_as_uint(bf[nt].x)), "r"(__float_as_uint(bf[nt].y)));
                }
        }
        __syncthreads();
    }

    #pragma unroll
    for (int mt = 0; mt < 2; mt++) {
        int r0 = row0 + warpM * 32 + mt * 16 + gid;
        #pragma unroll
        for (int nt = 0; nt < 4; nt++) {
            int c0 = col0 + warpN * 32 + nt * 8 + tig * 2;
            #pragma unroll
            for (int half = 0; half < 2; half++) {
                int r = r0 + half * 8;
                #pragma unroll
                for (int q = 0; q < 2; q++) {
                    int c = c0 + q;
                    float v = acc[mt][nt][half * 2 + q] + bias[c];
                    if (act == 1)      v = elu1(v) * 0.14433756729740643f;
                    else if (act == 2) v = elu1(v);
                    else if (act == 3) v = gelu_exact(v);
                    size_t idx = (size_t)r * N + c;
                    if (accFlag) v += Cout[idx];
                    Cout[idx] = v;
                }
            }
        }
    }
}

__global__ __launch_bounds__(256) void gemm_kernel(
        const float* __restrict__ A, const float* __restrict__ W,
        const float* __restrict__ bias, float* __restrict__ Cout,
        int K, int N, int act, int accFlag) {
    __shared__ float As[BM * BK];
    __shared__ float Bs[BN * BK];
    gemm_body(A, W, bias, Cout, K, N, act, accFlag, blockIdx.x, blockIdx.y, As, Bs);
}

// fused Q/K/V: blockIdx.y in [0,9): sel = y/3 chooses {q,k,v}, colBlk = y%3
__global__ __launch_bounds__(256) void qkv_kernel(
        const float* __restrict__ A,
        const float* __restrict__ wq, const float* __restrict__ wk, const float* __restrict__ wv,
        const float* __restrict__ bq, const float* __restrict__ bk, const float* __restrict__ bv,
        float* __restrict__ oq, float* __restrict__ ok, float* __restrict__ ov) {
    __shared__ float As[BM * BK];
    __shared__ float Bs[BN * BK];
    int sel = blockIdx.y / 3;
    int cb  = blockIdx.y % 3;
    const float* W  = sel == 0 ? wq : (sel == 1 ? wk : wv);
    const float* bi = sel == 0 ? bq : (sel == 1 ? bk : bv);
    float* Cout     = sel == 0 ? oq : (sel == 1 ? ok : ov);
    int act         = sel == 0 ? 1  : (sel == 1 ? 2  : 0);
    gemm_body(A, W, bi, Cout, CC, CC, act, 0, blockIdx.x, cb, As, Bs);
}

// ============================================================
// Kernel 4: linear attention core per (group, head)
// kv phase: 3x3 register tile per thread (16x16 thread grid covers 48x48)
// ============================================================
__global__ __launch_bounds__(256) void attn_kernel(
        const float* __restrict__ q, const float* __restrict__ k,
        const float* __restrict__ v, float* __restrict__ o,
        int N, int isCol) {
    extern __shared__ float sm[];
    float* ks   = sm;                 // N*48
    float* vs   = sm + N * DH;        // N*48
    float* kv   = vs + N * DH;        // 48*48
    float* ksum = kv + DH * DH;       // 48
    int g = blockIdx.x, h = blockIdx.y;
    int tid = threadIdx.x;

    for (int lin = tid; lin < N * (DH / 4); lin += 256) {
        int n = lin / (DH / 4);
        int j = lin - n * (DH / 4);
        int t = isCol ? ((((g >> 8) * SS + n) << 8) + (g & 255)) : g * N + n;
        size_t base = (size_t)t * CC + h * DH;
        ((float4*)ks)[n * (DH / 4) + j] = *(const float4*)(k + base + j * 4);
        ((float4*)vs)[n * (DH / 4) + j] = *(const float4*)(v + base + j * 4);
    }
    __syncthreads();

    if (tid < DH) {
        float s = 0.f;
        for (int n = 0; n < N; n++) s += ks[n * DH + tid];
        ksum[tid] = s;
    }
    // kv: 3x3 per-thread register tile
    {
        int dt = (tid >> 4) * 3;   // 0..45
        int et = (tid & 15) * 3;
        float c9[3][3];
        #pragma unroll
        for (int i = 0; i < 3; i++)
            #pragma unroll
            for (int j = 0; j < 3; j++) c9[i][j] = 0.f;
        for (int n = 0; n < N; n++) {
            float kk0 = ks[n * DH + dt],     kk1 = ks[n * DH + dt + 1], kk2 = ks[n * DH + dt + 2];
            float vv0 = vs[n * DH + et],     vv1 = vs[n * DH + et + 1], vv2 = vs[n * DH + et + 2];
            c9[0][0] += kk0 * vv0; c9[0][1] += kk0 * vv1; c9[0][2] += kk0 * vv2;
            c9[1][0] += kk1 * vv0; c9[1][1] += kk1 * vv1; c9[1][2] += kk1 * vv2;
            c9[2][0] += kk2 * vv0; c9[2][1] += kk2 * vv1; c9[2][2] += kk2 * vv2;
        }
        #pragma unroll
        for (int i = 0; i < 3; i++)
            #pragma unroll
            for (int j = 0; j < 3; j++)
                kv[(dt + i) * DH + et + j] = c9[i][j];
    }
    __syncthreads();

    for (int n = tid; n < N; n += 256) {
        int t = isCol ? ((((g >> 8) * SS + n) << 8) + (g & 255)) : g * N + n;
        size_t base = (size_t)t * CC + h * DH;
        float qr[DH];
        #pragma unroll
        for (int j = 0; j < DH / 4; j++) {
            float4 f = *(const float4*)(q + base + j * 4);
            qr[4*j] = f.x; qr[4*j+1] = f.y; qr[4*j+2] = f.z; qr[4*j+3] = f.w;
        }
        float qk = 0.f;
        #pragma unroll
        for (int d = 0; d < DH; d++) qk += qr[d] * ksum[d];
        float z = 1.0f / (qk + 1e-6f);
        float ov[DH];
        #pragma unroll
        for (int e = 0; e < DH; e++) ov[e] = 0.f;
        #pragma unroll
        for (int d = 0; d < DH; d++) {
            float qd = qr[d];
            const float4* kvr = (const float4*)&kv[d * DH];
            #pragma unroll
            for (int j = 0; j < DH / 4; j++) {
                float4 kk4 = kvr[j];
                ov[4*j]   += qd * kk4.x;
                ov[4*j+1] += qd * kk4.y;
                ov[4*j+2] += qd * kk4.z;
                ov[4*j+3] += qd * kk4.w;
            }
        }
        #pragma unroll
        for (int j = 0; j < DH / 4; j++) {
            float4 w4 = make_float4(ov[4*j]*z, ov[4*j+1]*z, ov[4*j+2]*z, ov[4*j+3]*z);
            *(float4*)(o + base + j * 4) = w4;
        }
    }
}

// ============================================================
// Kernel 5: head
// ============================================================
__global__ void final_kernel(const float* __restrict__ x,
                             const float* __restrict__ pw,
                             const float* __restrict__ pb,
                             float* __restrict__ out) {
    int t = blockIdx.x * 8 + threadIdx.y;
    int lane = threadIdx.x;
    const float* xr = x + (size_t)t * CC;
    float s = 0.f;
    #pragma unroll
    for (int i = 0; i < 6; i++) {
        int c = lane + i * 32;
        s += xr[c] * pw[c];
    }
    #pragma unroll
    for (int o = 16; o; o >>= 1) s += __shfl_xor_sync(0xffffffffu, s, o);
    if (lane == 0) {
        float ov = s + pb[0];
        float sp = (ov > 20.f) ? ov : log1pf(expf(ov));
        out[t] = 1.0f / (1.0f + expf(-sp));
    }
}

// ============================================================
// Host orchestration
// ============================================================
extern "C" void kernel_launch(void* const* d_in, const int* in_sizes, int n_in,
                              void* d_out, int out_size) {
    const int*   tokens = (const int*)  d_in[0];
    const float* emb    = (const float*)d_in[1];
    const float* proj_w = (const float*)d_in[2];
    const float* proj_b = (const float*)d_in[3];
    const float* ln_g   = (const float*)d_in[4];
    const float* ln_b   = (const float*)d_in[5];
    const float* wq     = (const float*)d_in[6];
    const float* wk     = (const float*)d_in[7];
    const float* wv     = (const float*)d_in[8];
    const float* wo     = (const float*)d_in[9];
    const float* bq     = (const float*)d_in[10];
    const float* bk     = (const float*)d_in[11];
    const float* bv     = (const float*)d_in[12];
    const float* bo     = (const float*)d_in[13];
    const float* ffn_w1 = (const float*)d_in[14];
    const float* ffn_b1 = (const float*)d_in[15];
    const float* ffn_w2 = (const float*)d_in[16];
    const float* ffn_b2 = (const float*)d_in[17];
    const float* pw_w   = (const float*)d_in[18];
    const float* pw_b   = (const float*)d_in[19];
    float* out = (float*)d_out;

    float *px, *ph, *pq, *pk, *pv, *pf;
    cudaGetSymbolAddress((void**)&px, g_x);
    cudaGetSymbolAddress((void**)&ph, g_h);
    cudaGetSymbolAddress((void**)&pq, g_q);
    cudaGetSymbolAddress((void**)&pk, g_k);
    cudaGetSymbolAddress((void**)&pv, g_v);
    cudaGetSymbolAddress((void**)&pf, g_f1);

    cudaFuncSetAttribute(attn_kernel, cudaFuncAttributeMaxDynamicSharedMemorySize, 110592);

    dim3 lnBlk(32, 8);
    dim3 gQKV(TT / BM, 9);
    dim3 g192(TT / BM, CC / BN);
    dim3 g768(TT / BM, C4 / BN);

    embed_kernel<<<TT, CC>>>(tokens, emb, proj_w, proj_b, px);

    for (int i = 0; i < NBLK; i++) {
        for (int dir = 0; dir < 2; dir++) {
            const float* lg = ln_g + (size_t)(i * 3 + dir) * CC;
            const float* lb = ln_b + (size_t)(i * 3 + dir) * CC;
            ln_kernel<<<TT / 8, lnBlk>>>(px, ph, lg, lb);

            size_t woff = ((size_t)i * 2 + dir) * CC * CC;
            size_t boff = ((size_t)i * 2 + dir) * CC;
            qkv_kernel<<<gQKV, 256>>>(ph, wq + woff, wk + woff, wv + woff,
                                      bq + boff, bk + boff, bv + boff, pq, pk, pv);

            int N      = (dir == 0) ? LL : SS;
            int groups = (dir == 0) ? BB * SS : BB * LL;
            size_t smem = (size_t)(2 * N * DH + DH * DH + DH) * sizeof(float);
            attn_kernel<<<dim3(groups, HH), 256, smem>>>(pq, pk, pv, ph, N, dir);

            gemm_kernel<<<g192, 256>>>(ph, wo + woff, bo + boff, px, CC, CC, 0, 1);
        }
        const float* lg = ln_g + (size_t)(i * 3 + 2) * CC;
        const float* lb = ln_b + (size_t)(i * 3 + 2) * CC;
        ln_kernel<<<TT / 8, lnBlk>>>(px, ph, lg, lb);
        gemm_kernel<<<g768, 256>>>(ph, ffn_w1 + (size_t)i * C4 * CC, ffn_b1 + (size_t)i * C4,
                                   pf, CC, C4, 3, 0);
        gemm_kernel<<<g192, 256>>>(pf, ffn_w2 + (size_t)i * CC * C4, ffn_b2 + (size_t)i * CC,
                                   px, C4, CC, 0, 1);
    }

    final_kernel<<<TT / 8, lnBlk>>>(px, pw_w, pw_b, out);
}

// round 4
// speedup vs baseline: 1.0015x; 1.0015x over previous
#include <cuda_runtime.h>
#include <math.h>

// ---------------- problem constants ----------------
#define BB 2
#define SS 64
#define LL 256
#define CC 192
#define C4 768
#define HH 4
#define DH 48
#define TT (BB*SS*LL)      // 32768 tokens
#define NBLK 6

// ---------------- scratch ----------------
__device__ float g_x[TT*CC];
__device__ float g_h[TT*CC];
__device__ float g_q[TT*CC];
__device__ float g_k[TT*CC];
__device__ float g_v[TT*CC];
__device__ float g_f1[TT*C4];

__device__ __forceinline__ float elu1(float v) { return v > 0.0f ? v + 1.0f : expf(v); }
__device__ __forceinline__ float gelu_exact(float v) {
    return 0.5f * v * (1.0f + erff(v * 0.70710678118654752f));
}

// ============================================================
// Kernel 1: embed + proj + rotary
// ============================================================
__global__ void embed_kernel(const int* __restrict__ tokens,
                             const float* __restrict__ emb,
                             const float* __restrict__ pw,
                             const float* __restrict__ pb,
                             float* __restrict__ out) {
    int t = blockIdx.x;
    int c = threadIdx.x;
    __shared__ float e[64];
    __shared__ float xv[CC];
    __shared__ float invf[96];
    if (c < 64) e[c] = emb[tokens[t] * 64 + c];
    if (c >= 64 && c < 160) {
        int j = c - 64;
        invf[j] = powf(10000.0f, -(float)j / 96.0f);
    }
    __syncthreads();
    float s = pb[c];
    const float* wr = pw + c * 64;
    #pragma unroll
    for (int i = 0; i < 64; i++) s += e[i] * wr[i];
    xv[c] = s;
    __syncthreads();
    int l = t & (LL - 1);
    int c2 = (c < 96) ? c : c - 96;
    float a = (float)l * invf[c2];
    float cs = cosf(a), sn = sinf(a);
    float rot = (c < 96) ? -xv[c + 96] : xv[c - 96];
    out[(size_t)t * CC + c] = s * cs + rot * sn;
}

// ============================================================
// Kernel 2: LayerNorm over channels
// ============================================================
__global__ void ln_kernel(const float* __restrict__ x, float* __restrict__ h,
                          const float* __restrict__ g, const float* __restrict__ b) {
    int t = blockIdx.x * 8 + threadIdx.y;
    int lane = threadIdx.x;
    const float* xr = x + (size_t)t * CC;
    float v[6];
    float s = 0.f, ss = 0.f;
    #pragma unroll
    for (int i = 0; i < 6; i++) {
        v[i] = xr[lane + i * 32];
        s += v[i]; ss += v[i] * v[i];
    }
    #pragma unroll
    for (int o = 16; o; o >>= 1) {
        s  += __shfl_xor_sync(0xffffffffu, s, o);
        ss += __shfl_xor_sync(0xffffffffu, ss, o);
    }
    float m   = s * (1.0f / CC);
    float var = ss * (1.0f / CC) - m * m;
    float r   = rsqrtf(var + 1e-5f);
    float* hr = h + (size_t)t * CC;
    #pragma unroll
    for (int i = 0; i < 6; i++) {
        int c = lane + i * 32;
        hr[c] = (v[i] - m) * r * g[c] + b[c];
    }
}

// ============================================================
// TF32 tensor-core GEMM body, fragment-major shared layout.
// C[t,o] = act( A[t,:K] . W[o,:K] + bias[o] ) (+C)
// Block tile 128x64, 8 warps (4x2), warp 32x32, mma m16n8k8 tf32.
// Shared A: [mtile(8)][ktile(2)][lane(32)][slot(4)]  (float4 per lane)
// Shared B: [ntile(8)][ktile(2)][lane(32)][slot(2)]  (float2 per lane)
// ============================================================
#define BM 128
#define BN 64
#define BK 16

__device__ __forceinline__ void gemm_body(
        const float* __restrict__ A, const float* __restrict__ W,
        const float* __restrict__ bias, float* __restrict__ Cout,
        int K, int N, int act, int accFlag, int rowBlk, int colBlk,
        float* As, float* Bs) {
    int tid  = threadIdx.x;
    int lane = tid & 31;
    int warp = tid >> 5;
    int warpM = warp >> 1;
    int warpN = warp & 1;
    int gid = lane >> 2;
    int tig = lane & 3;
    int row0 = rowBlk * BM;
    int col0 = colBlk * BN;

    float acc[2][4][4];
    #pragma unroll
    for (int i = 0; i < 2; i++)
        #pragma unroll
        for (int j = 0; j < 4; j++)
            #pragma unroll
            for (int q = 0; q < 4; q++) acc[i][j][q] = 0.f;

    // staging indices
    int am = tid >> 1;                 // with i-loop: lin = tid + i*256 -> m = lin>>2... use explicit below
    (void)am;
    float4 aPre[2]; float4 bPre;
    {   // preload k0 = 0
        #pragma unroll
        for (int i = 0; i < 2; i++) {
            int lin = tid + i * 256;
            int m  = lin >> 2;
            int kq = (lin & 3) << 2;
            aPre[i] = *(const float4*)&A[(size_t)(row0 + m) * K + kq];
        }
        int n  = tid >> 2;
        int kq = (tid & 3) << 2;
        bPre = *(const float4*)&W[(size_t)(col0 + n) * K + kq];
    }

    for (int k0 = 0; k0 < K; k0 += BK) {
        // ---- store staged regs into fragment-major smem ----
        #pragma unroll
        for (int i = 0; i < 2; i++) {
            int lin = tid + i * 256;
            int m  = lin >> 2;
            int kq = (lin & 3) << 2;
            int mtile = m >> 4, r = m & 15;
            float fv[4] = {aPre[i].x, aPre[i].y, aPre[i].z, aPre[i].w};
            #pragma unroll
            for (int j = 0; j < 4; j++) {
                int k = kq + j;
                int ktile = k >> 3, kk = k & 7;
                int idx = (((mtile * 2 + ktile) * 32) + (r & 7) * 4 + (kk & 3)) * 4
                          + (r >> 3) + ((kk >> 2) << 1);
                As[idx] = fv[j];
            }
        }
        {
            int n  = tid >> 2;
            int kq = (tid & 3) << 2;
            int ntile = n >> 3, c = n & 7;
            float fv[4] = {bPre.x, bPre.y, bPre.z, bPre.w};
            #pragma unroll
            for (int j = 0; j < 4; j++) {
                int k = kq + j;
                int ktile = k >> 3, kk = k & 7;
                int idx = (((ntile * 2 + ktile) * 32) + c * 4 + (kk & 3)) * 2 + (kk >> 2);
                Bs[idx] = fv[j];
            }
        }
        __syncthreads();

        // ---- prefetch next k-tile ----
        if (k0 + BK < K) {
            #pragma unroll
            for (int i = 0; i < 2; i++) {
                int lin = tid + i * 256;
                int m  = lin >> 2;
                int kq = (lin & 3) << 2;
                aPre[i] = *(const float4*)&A[(size_t)(row0 + m) * K + k0 + BK + kq];
            }
            int n  = tid >> 2;
            int kq = (tid & 3) << 2;
            bPre = *(const float4*)&W[(size_t)(col0 + n) * K + k0 + BK + kq];
        }

        // ---- compute ----
        #pragma unroll
        for (int ktile = 0; ktile < 2; ktile++) {
            float4 af[2]; float2 bf[4];
            #pragma unroll
            for (int mt = 0; mt < 2; mt++) {
                int mtile = warpM * 2 + mt;
                af[mt] = ((const float4*)As)[(mtile * 2 + ktile) * 32 + lane];
            }
            #pragma unroll
            for (int nt = 0; nt < 4; nt++) {
                int ntile = warpN * 4 + nt;
                bf[nt] = ((const float2*)Bs)[(ntile * 2 + ktile) * 32 + lane];
            }
            #pragma unroll
            for (int mt = 0; mt < 2; mt++)
                #pragma unroll
                for (int nt = 0; nt < 4; nt++) {
                    asm volatile(
                        "mma.sync.aligned.m16n8k8.row.col.f32.tf32.tf32.f32 "
                        "{%0,%1,%2,%3}, {%4,%5,%6,%7}, {%8,%9}, {%0,%1,%2,%3};"
                        : "+f"(acc[mt][nt][0]), "+f"(acc[mt][nt][1]),
                          "+f"(acc[mt][nt][2]), "+f"(acc[mt][nt][3])
                        : "r"(__float_as_uint(af[mt].x)), "r"(__float_as_uint(af[mt].y)),
                          "r"(__float_as_uint(af[mt].z)), "r"(__float_as_uint(af[mt].w)),
                          "r"(__float_as_uint(bf[nt].x)), "r"(__float_as_uint(bf[nt].y)));
                }
        }
        __syncthreads();
    }

    #pragma unroll
    for (int mt = 0; mt < 2; mt++) {
        int r0 = row0 + warpM * 32 + mt * 16 + gid;
        #pragma unroll
        for (int nt = 0; nt < 4; nt++) {
            int c0 = col0 + warpN * 32 + nt * 8 + tig * 2;
            #pragma unroll
            for (int half = 0; half < 2; half++) {
                int r = r0 + half * 8;
                #pragma unroll
                for (int q = 0; q < 2; q++) {
                    int c = c0 + q;
                    float v = acc[mt][nt][half * 2 + q] + bias[c];
                    if (act == 1)      v = elu1(v) * 0.14433756729740643f;
                    else if (act == 2) v = elu1(v);
                    else if (act == 3) v = gelu_exact(v);
                    size_t idx = (size_t)r * N + c;
                    if (accFlag) v += Cout[idx];
                    Cout[idx] = v;
                }
            }
        }
    }
}

__global__ __launch_bounds__(256) void gemm_kernel(
        const float* __restrict__ A, const float* __restrict__ W,
        const float* __restrict__ bias, float* __restrict__ Cout,
        int K, int N, int act, int accFlag) {
    __shared__ float As[BM * BK];
    __shared__ float Bs[BN * BK];
    gemm_body(A, W, bias, Cout, K, N, act, accFlag, blockIdx.x, blockIdx.y, As, Bs);
}

// fused Q/K/V: blockIdx.y in [0,9): sel = y/3 chooses {q,k,v}, colBlk = y%3
__global__ __launch_bounds__(256) void qkv_kernel(
        const float* __restrict__ A,
        const float* __restrict__ wq, const float* __restrict__ wk, const float* __restrict__ wv,
        const float* __restrict__ bq, const float* __restrict__ bk, const float* __restrict__ bv,
        float* __restrict__ oq, float* __restrict__ ok, float* __restrict__ ov) {
    __shared__ float As[BM * BK];
    __shared__ float Bs[BN * BK];
    int sel = blockIdx.y / 3;
    int cb  = blockIdx.y % 3;
    const float* W  = sel == 0 ? wq : (sel == 1 ? wk : wv);
    const float* bi = sel == 0 ? bq : (sel == 1 ? bk : bv);
    float* Cout     = sel == 0 ? oq : (sel == 1 ? ok : ov);
    int act         = sel == 0 ? 1  : (sel == 1 ? 2  : 0);
    gemm_body(A, W, bi, Cout, CC, CC, act, 0, blockIdx.x, cb, As, Bs);
}

// ============================================================
// Kernel 4: linear attention core per (group, head)
// kv phase: 3x3 register tile per thread (16x16 thread grid covers 48x48)
// ============================================================
__global__ __launch_bounds__(256) void attn_kernel(
        const float* __restrict__ q, const float* __restrict__ k,
        const float* __restrict__ v, float* __restrict__ o,
        int N, int isCol) {
    extern __shared__ float sm[];
    float* ks   = sm;                 // N*48
    float* vs   = sm + N * DH;        // N*48
    float* kv   = vs + N * DH;        // 48*48
    float* ksum = kv + DH * DH;       // 48
    int g = blockIdx.x, h = blockIdx.y;
    int tid = threadIdx.x;

    for (int lin = tid; lin < N * (DH / 4); lin += 256) {
        int n = lin / (DH / 4);
        int j = lin - n * (DH / 4);
        int t = isCol ? ((((g >> 8) * SS + n) << 8) + (g & 255)) : g * N + n;
        size_t base = (size_t)t * CC + h * DH;
        ((float4*)ks)[n * (DH / 4) + j] = *(const float4*)(k + base + j * 4);
        ((float4*)vs)[n * (DH / 4) + j] = *(const float4*)(v + base + j * 4);
    }
    __syncthreads();

    if (tid < DH) {
        float s = 0.f;
        for (int n = 0; n < N; n++) s += ks[n * DH + tid];
        ksum[tid] = s;
    }
    // kv: 3x3 per-thread register tile
    {
        int dt = (tid >> 4) * 3;   // 0..45
        int et = (tid & 15) * 3;
        float c9[3][3];
        #pragma unroll
        for (int i = 0; i < 3; i++)
            #pragma unroll
            for (int j = 0; j < 3; j++) c9[i][j] = 0.f;
        for (int n = 0; n < N; n++) {
            float kk0 = ks[n * DH + dt],     kk1 = ks[n * DH + dt + 1], kk2 = ks[n * DH + dt + 2];
            float vv0 = vs[n * DH + et],     vv1 = vs[n * DH + et + 1], vv2 = vs[n * DH + et + 2];
            c9[0][0] += kk0 * vv0; c9[0][1] += kk0 * vv1; c9[0][2] += kk0 * vv2;
            c9[1][0] += kk1 * vv0; c9[1][1] += kk1 * vv1; c9[1][2] += kk1 * vv2;
            c9[2][0] += kk2 * vv0; c9[2][1] += kk2 * vv1; c9[2][2] += kk2 * vv2;
        }
        #pragma unroll
        for (int i = 0; i < 3; i++)
            #pragma unroll
            for (int j = 0; j < 3; j++)
                kv[(dt + i) * DH + et + j] = c9[i][j];
    }
    __syncthreads();

    for (int n = tid; n < N; n += 256) {
        int t = isCol ? ((((g >> 8) * SS + n) << 8) + (g & 255)) : g * N + n;
        size_t base = (size_t)t * CC + h * DH;
        float qr[DH];
        #pragma unroll
        for (int j = 0; j < DH / 4; j++) {
            float4 f = *(const float4*)(q + base + j * 4);
            qr[4*j] = f.x; qr[4*j+1] = f.y; qr[4*j+2] = f.z; qr[4*j+3] = f.w;
        }
        float qk = 0.f;
        #pragma unroll
        for (int d = 0; d < DH; d++) qk += qr[d] * ksum[d];
        float z = 1.0f / (qk + 1e-6f);
        float ov[DH];
        #pragma unroll
        for (int e = 0; e < DH; e++) ov[e] = 0.f;
        #pragma unroll
        for (int d = 0; d < DH; d++) {
            float qd = qr[d];
            const float4* kvr = (const float4*)&kv[d * DH];
            #pragma unroll
            for (int j = 0; j < DH / 4; j++) {
                float4 kk4 = kvr[j];
                ov[4*j]   += qd * kk4.x;
                ov[4*j+1] += qd * kk4.y;
                ov[4*j+2] += qd * kk4.z;
                ov[4*j+3] += qd * kk4.w;
            }
        }
        #pragma unroll
        for (int j = 0; j < DH / 4; j++) {
            float4 w4 = make_float4(ov[4*j]*z, ov[4*j+1]*z, ov[4*j+2]*z, ov[4*j+3]*z);
            *(float4*)(o + base + j * 4) = w4;
        }
    }
}

// ============================================================
// Kernel 5: head
// ============================================================
__global__ void final_kernel(const float* __restrict__ x,
                             const float* __restrict__ pw,
                             const float* __restrict__ pb,
                             float* __restrict__ out) {
    int t = blockIdx.x * 8 + threadIdx.y;
    int lane = threadIdx.x;
    const float* xr = x + (size_t)t * CC;
    float s = 0.f;
    #pragma unroll
    for (int i = 0; i < 6; i++) {
        int c = lane + i * 32;
        s += xr[c] * pw[c];
    }
    #pragma unroll
    for (int o = 16; o; o >>= 1) s += __shfl_xor_sync(0xffffffffu, s, o);
    if (lane == 0) {
        float ov = s + pb[0];
        float sp = (ov > 20.f) ? ov : log1pf(expf(ov));
        out[t] = 1.0f / (1.0f + expf(-sp));
    }
}

// ============================================================
// Host orchestration
// ============================================================
extern "C" void kernel_launch(void* const* d_in, const int* in_sizes, int n_in,
                              void* d_out, int out_size) {
    const int*   tokens = (const int*)  d_in[0];
    const float* emb    = (const float*)d_in[1];
    const float* proj_w = (const float*)d_in[2];
    const float* proj_b = (const float*)d_in[3];
    const float* ln_g   = (const float*)d_in[4];
    const float* ln_b   = (const float*)d_in[5];
    const float* wq     = (const float*)d_in[6];
    const float* wk     = (const float*)d_in[7];
    const float* wv     = (const float*)d_in[8];
    const float* wo     = (const float*)d_in[9];
    const float* bq     = (const float*)d_in[10];
    const float* bk     = (const float*)d_in[11];
    const float* bv     = (const float*)d_in[12];
    const float* bo     = (const float*)d_in[13];
    const float* ffn_w1 = (const float*)d_in[14];
    const float* ffn_b1 = (const float*)d_in[15];
    const float* ffn_w2 = (const float*)d_in[16];
    const float* ffn_b2 = (const float*)d_in[17];
    const float* pw_w   = (const float*)d_in[18];
    const float* pw_b   = (const float*)d_in[19];
    float* out = (float*)d_out;

    float *px, *ph, *pq, *pk, *pv, *pf;
    cudaGetSymbolAddress((void**)&px, g_x);
    cudaGetSymbolAddress((void**)&ph, g_h);
    cudaGetSymbolAddress((void**)&pq, g_q);
    cudaGetSymbolAddress((void**)&pk, g_k);
    cudaGetSymbolAddress((void**)&pv, g_v);
    cudaGetSymbolAddress((void**)&pf, g_f1);

    cudaFuncSetAttribute(attn_kernel, cudaFuncAttributeMaxDynamicSharedMemorySize, 110592);

    dim3 lnBlk(32, 8);
    dim3 gQKV(TT / BM, 9);
    dim3 g192(TT / BM, CC / BN);
    dim3 g768(TT / BM, C4 / BN);

    embed_kernel<<<TT, CC>>>(tokens, emb, proj_w, proj_b, px);

    for (int i = 0; i < NBLK; i++) {
        for (int dir = 0; dir < 2; dir++) {
            const float* lg = ln_g + (size_t)(i * 3 + dir) * CC;
            const float* lb = ln_b + (size_t)(i * 3 + dir) * CC;
            ln_kernel<<<TT / 8, lnBlk>>>(px, ph, lg, lb);

            size_t woff = ((size_t)i * 2 + dir) * CC * CC;
            size_t boff = ((size_t)i * 2 + dir) * CC;
            qkv_kernel<<<gQKV, 256>>>(ph, wq + woff, wk + woff, wv + woff,
                                      bq + boff, bk + boff, bv + boff, pq, pk, pv);

            int N      = (dir == 0) ? LL : SS;
            int groups = (dir == 0) ? BB * SS : BB * LL;
            size_t smem = (size_t)(2 * N * DH + DH * DH + DH) * sizeof(float);
            attn_kernel<<<dim3(groups, HH), 256, smem>>>(pq, pk, pv, ph, N, dir);

            gemm_kernel<<<g192, 256>>>(ph, wo + woff, bo + boff, px, CC, CC, 0, 1);
        }
        const float* lg = ln_g + (size_t)(i * 3 + 2) * CC;
        const float* lb = ln_b + (size_t)(i * 3 + 2) * CC;
        ln_kernel<<<TT / 8, lnBlk>>>(px, ph, lg, lb);
        gemm_kernel<<<g768, 256>>>(ph, ffn_w1 + (size_t)i * C4 * CC, ffn_b1 + (size_t)i * C4,
                                   pf, CC, C4, 3, 0);
        gemm_kernel<<<g192, 256>>>(pf, ffn_w2 + (size_t)i * CC * C4, ffn_b2 + (size_t)i * CC,
                                   px, C4, CC, 0, 1);
    }

    final_kernel<<<TT / 8, lnBlk>>>(px, pw_w, pw_b, out);
}